// round 9
// baseline (speedup 1.0000x reference)
#include <cuda_runtime.h>

// GaussianUpsampling: out[b,c,f] = sum_j softmax_j(-0.1*(f - c_j)^2) * x[b,c,j]
//   c = cumsum(w) - 0.5*w   (bit-matches JAX associative_scan Brent-Kung tree)
// B=16, C=256, T_text=512, T_feat=4096. Masks structurally all-true.
//
// R9: one CTA = full 256 channels x 32 frames (512 threads, grid 128x16).
// x smem transposed [channel][token] with 16B-unit XOR swizzle -> STS.128
// and 1 LDS.128 per 4 tokens per channel row. Analytic softmax max kept.

#define NB 16
#define NC 256
#define TT 512
#define TFEAT 4096
#define DELTA_F 0.1f
#define TILE_F 32
#define NTILES (TFEAT / TILE_F)   // 128
#define MAXBAND 32
#define NTHREADS 512

__device__ float g_c[NB * TT];
__device__ int2  g_band[NB * NTILES];

#define FMA2(acc, a, b) \
  asm("fma.rn.f32x2 %0, %1, %2, %0;" : "+l"(acc) : "l"(a), "l"(b))
#define MUL2(out, a, b) \
  asm("mul.rn.f32x2 %0, %1, %2;" : "=l"(out) : "l"(a), "l"(b))
#define PACK2(out, lo, hi) \
  asm("mov.b64 %0, {%1, %2};" : "=l"(out) : "f"(lo), "f"(hi))
#define UNPACK2(lo, hi, in) \
  asm("mov.b64 {%0, %1}, %2;" : "=f"(lo), "=f"(hi) : "l"(in))

__device__ __forceinline__ int lower_bound_s(const float* c, float v) {
  int lo = 0, hi = TT;
  while (lo < hi) { int m = (lo + hi) >> 1; if (c[m] < v) lo = m + 1; else hi = m; }
  return lo;
}

// ---------------------------------------------------------------------------
// Brent-Kung scan replicating jax.lax.associative_scan's exact add tree,
// then per-tile band computation. 16 blocks x 256 threads (best measured).
// ---------------------------------------------------------------------------
__global__ void cumsum_kernel(const float* __restrict__ w) {
  __shared__ float buf[1024];
  __shared__ float c_sh[TT];
  const int b = blockIdx.x;
  const int tid = threadIdx.x;
  const float* wb = w + b * TT;

  for (int i = tid; i < TT; i += blockDim.x) buf[i] = wb[i];
  __syncthreads();

  for (int size = TT; size > 1; size >>= 1) {   // up-sweep
    int off = 1024 - 2 * size, noff = 1024 - size, half = size >> 1;
    for (int i = tid; i < half; i += blockDim.x)
      buf[noff + i] = buf[off + 2 * i] + buf[off + 2 * i + 1];
    __syncthreads();
  }
  for (int size = 2; size <= TT; size <<= 1) {  // down-sweep
    int off = 1024 - 2 * size, offp = 1024 - size, half = size >> 1;
    for (int i = tid; i < half; i += blockDim.x) {
      float sp = buf[offp + i];
      if (2 * i + 2 < size) {
        float t = sp + buf[off + 2 * i + 2];
        buf[off + 2 * i + 1] = sp;
        buf[off + 2 * i + 2] = t;
      } else {
        buf[off + 2 * i + 1] = sp;
      }
    }
    __syncthreads();
  }
  for (int i = tid; i < TT; i += blockDim.x) {
    float cv = buf[i] - 0.5f * wb[i];
    c_sh[i] = cv;
    g_c[b * TT + i] = cv;
  }
  __syncthreads();

  for (int t = tid; t < NTILES; t += blockDim.x) {
    const float R = 18.0f;  // exp(-0.1*18^2) ~ 8e-15 relative
    float tmin = (float)(t * TILE_F);
    float tmax = tmin + (float)(TILE_F - 1);
    int jlo = lower_bound_s(c_sh, tmin - R);
    int jhi = lower_bound_s(c_sh, tmax + R);
    int plo = lower_bound_s(c_sh, tmin);
    int phi = lower_bound_s(c_sh, tmax);
    jlo = min(jlo, max(plo - 1, 0));          // always include nearest tokens
    jhi = max(jhi, min(phi + 1, TT));
    jlo &= ~3;                                 // float4 alignment
    if (jhi - jlo > MAXBAND) {                 // statistically impossible cap
      int slack = (max(0, (plo - 1) - jlo)) & ~3;
      int need  = jhi - jlo - MAXBAND;
      int adv   = min((need + 3) & ~3, slack);
      jlo += adv;
      jhi = min(jhi, jlo + MAXBAND);
    }
    g_band[b * NTILES + t] = make_int2(jlo, jhi);
  }
}

// ---------------------------------------------------------------------------
// Fused banded softmax + GEMM. Block = (32-frame tile, batch), 512 threads,
// full 256 channels. Thread tile 2ch x 8fr; regs <= 64 -> 2 CTAs/SM.
// x_sT[c][tok]: rows of 32 floats (128B), 16B unit swizzled by (c>>1)&7.
// ---------------------------------------------------------------------------
__global__ __launch_bounds__(NTHREADS, 2) void gauss_kernel(
    const float* __restrict__ x, float* __restrict__ out)
{
  __shared__ __align__(16) float x_sT[NC][TILE_F];        // 32 KB, swizzled
  __shared__ __align__(16) float attn_s[MAXBAND][TILE_F]; // unnormalized E
  __shared__ float c_sh[MAXBAND];
  __shared__ float ps[16][TILE_F];
  __shared__ __align__(16) float r_s[TILE_F];

  const int b   = blockIdx.y;
  const int f0  = blockIdx.x * TILE_F;
  const int tid = threadIdx.x;

  const int2 bd = g_band[b * NTILES + blockIdx.x];
  const int jlo = bd.x;
  const int nband  = bd.y - jlo;
  const int nband4 = (nband + 3) & ~3;

  // ---- phase A: issue x loads (4 channels x 4 tokens per thread) -------
  const int tq = tid & 7;            // token quad
  const int c0 = tid >> 3;           // channel base 0..63 (stride 64)
  const int row0 = 4 * tq;
  const bool doload = row0 < nband4;
  float4 v[4];
  if (doload) {
    const bool full = (row0 + 4 <= nband);
    const float* xb = x + (size_t)b * NC * TT + jlo + row0;
    #pragma unroll
    for (int p = 0; p < 4; p++) {
      const int c = c0 + 64 * p;
      const float* src = xb + (size_t)c * TT;
      if (full) {
        v[p] = *(const float4*)src;
      } else {
        v[p].x = (row0     < nband) ? src[0] : 0.0f;
        v[p].y = (row0 + 1 < nband) ? src[1] : 0.0f;
        v[p].z = (row0 + 2 < nband) ? src[2] : 0.0f;
        v[p].w = (row0 + 3 < nband) ? src[3] : 0.0f;
      }
    }
  }

  if (tid < MAXBAND)
    c_sh[tid] = (tid < nband) ? g_c[b * TT + jlo + tid] : 3.0e38f;
  __syncthreads();                                   // #1: c_sh ready

  // ---- phase B: analytic softmax max + exp + partial sums; x STS -------
  const int fE   = tid & 31;         // frame within tile
  const int kgrp = tid >> 5;         // 0..15
  {
    const float tf = (float)(f0 + fE);
    int lo = 0, hi = nband;          // nearest center (<=5 steps)
    while (lo < hi) { int mid = (lo + hi) >> 1; if (c_sh[mid] < tf) lo = mid + 1; else hi = mid; }
    float dR = (lo < nband) ? (c_sh[lo] - tf) : 3.0e38f;
    float dL = (lo > 0)     ? (tf - c_sh[lo - 1]) : 3.0e38f;
    float dmin = fminf(dL, dR);
    const float m = -DELTA_F * (dmin * dmin);        // exact band max

    float sloc = 0.0f;
    #pragma unroll
    for (int u = 0; u < 2; u++) {
      const int kk = kgrp + 16 * u;
      float E = 0.0f;
      if (kk < nband) {
        float d = tf - c_sh[kk];
        E = __expf(-DELTA_F * (d * d) - m);          // <= 1, NaN-safe
      }
      attn_s[kk][fE] = E;
      sloc += E;
    }
    ps[kgrp][fE] = sloc;
  }
  if (doload) {
    #pragma unroll
    for (int p = 0; p < 4; p++) {
      const int c  = c0 + 64 * p;
      const int pu = tq ^ ((c >> 1) & 7);            // 16B-unit swizzle
      *(float4*)&x_sT[c][4 * pu] = v[p];
    }
  }
  __syncthreads();                                   // #2: attn_s, x_sT, ps ready
  if (tid < TILE_F) {
    float s = ps[0][tid];
    #pragma unroll
    for (int k = 1; k < 16; k++) s += ps[k][tid];
    r_s[tid] = 1.0f / s;
  }

  // ---- main FMA loop: per 4 tokens: 2 LDS.128 x + 8 LDS.128 attn -------
  const int cgrp = tid >> 2;          // 0..127: channels 2*cgrp, 2*cgrp+1
  const int fg   = (tid & 3) << 3;    // frame base (8 frames)
  const float* xr0 = &x_sT[2 * cgrp][0];
  const float* xr1 = &x_sT[2 * cgrp + 1][0];

  unsigned long long acc2[2][4];
  #pragma unroll
  for (int ci = 0; ci < 2; ci++)
    #pragma unroll
    for (int q = 0; q < 4; q++) acc2[ci][q] = 0ull;

  for (int kk0 = 0; kk0 < nband4; kk0 += 4) {
    const int pu = (kk0 >> 2) ^ (cgrp & 7);
    float4 xa = *(const float4*)&xr0[4 * pu];        // c0, tokens kk0..+3
    float4 xb4 = *(const float4*)&xr1[4 * pu];       // c1, tokens kk0..+3
    float xav[4] = {xa.x, xa.y, xa.z, xa.w};
    float xbv[4] = {xb4.x, xb4.y, xb4.z, xb4.w};
    #pragma unroll
    for (int u = 0; u < 4; u++) {
      const int kk = kk0 + u;
      ulonglong2 a01 = *(const ulonglong2*)&attn_s[kk][fg];
      ulonglong2 a23 = *(const ulonglong2*)&attn_s[kk][fg + 4];
      unsigned long long xp0, xp1;
      PACK2(xp0, xav[u], xav[u]);
      PACK2(xp1, xbv[u], xbv[u]);
      FMA2(acc2[0][0], xp0, a01.x);
      FMA2(acc2[0][1], xp0, a01.y);
      FMA2(acc2[0][2], xp0, a23.x);
      FMA2(acc2[0][3], xp0, a23.y);
      FMA2(acc2[1][0], xp1, a01.x);
      FMA2(acc2[1][1], xp1, a01.y);
      FMA2(acc2[1][2], xp1, a23.x);
      FMA2(acc2[1][3], xp1, a23.y);
    }
  }
  __syncthreads();                                   // #3: r_s ready

  // ---- epilogue: normalize by r[f], store ------------------------------
  ulonglong2 r01 = *(const ulonglong2*)&r_s[fg];
  ulonglong2 r23 = *(const ulonglong2*)&r_s[fg + 4];
  unsigned long long rp[4] = {r01.x, r01.y, r23.x, r23.y};

  #pragma unroll
  for (int ci = 0; ci < 2; ci++) {
    float r[8];
    #pragma unroll
    for (int q = 0; q < 4; q++) {
      unsigned long long t;
      MUL2(t, acc2[ci][q], rp[q]);
      UNPACK2(r[2 * q], r[2 * q + 1], t);
    }
    const int ch = 2 * cgrp + ci;
    float* o = out + ((size_t)b * NC + ch) * TFEAT + f0 + fg;
    *(float4*)&o[0] = make_float4(r[0], r[1], r[2], r[3]);
    *(float4*)&o[4] = make_float4(r[4], r[5], r[6], r[7]);
  }
}

extern "C" void kernel_launch(void* const* d_in, const int* in_sizes, int n_in,
                              void* d_out, int out_size) {
  const float* x = (const float*)d_in[0];   // (B, C, T_text) fp32
  const float* w = (const float*)d_in[1];   // (B, T_text)    fp32
  float* out = (float*)d_out;               // (B, C, T_feat) fp32

  cumsum_kernel<<<NB, 256>>>(w);
  gauss_kernel<<<dim3(NTILES, NB), NTHREADS>>>(x, out);
}

// round 10
// speedup vs baseline: 1.0054x; 1.0054x over previous
#include <cuda_runtime.h>

// GaussianUpsampling: out[b,c,f] = sum_j softmax_j(-0.1*(f - c_j)^2) * x[b,c,j]
//   c = cumsum(w) - 0.5*w   (bit-matches JAX associative_scan Brent-Kung tree)
// B=16, C=256, T_text=512, T_feat=4096. Masks structurally all-true.
//
// R10: gauss tile = 16 frames x 256 channels (256 threads, grid 256x16).
// Softmax/exp computed once per full channel set (MUFU work halved) and the
// shorter frame tile shrinks the token band (~19% fewer FMAs per output).
// Thread tile 2ch x 8fr, R5's proven token-major XOR-swizzled x smem.

#define NB 16
#define NC 256
#define TT 512
#define TFEAT 4096
#define DELTA_F 0.1f
#define TILE_F 16
#define NTILES (TFEAT / TILE_F)   // 256
#define MAXBAND 32
#define NTHREADS 256

__device__ float g_c[NB * TT];
__device__ int2  g_band[NB * NTILES];

#define FMA2(acc, a, b) \
  asm("fma.rn.f32x2 %0, %1, %2, %0;" : "+l"(acc) : "l"(a), "l"(b))
#define MUL2(out, a, b) \
  asm("mul.rn.f32x2 %0, %1, %2;" : "=l"(out) : "l"(a), "l"(b))
#define PACK2(out, lo, hi) \
  asm("mov.b64 %0, {%1, %2};" : "=l"(out) : "f"(lo), "f"(hi))
#define UNPACK2(lo, hi, in) \
  asm("mov.b64 {%0, %1}, %2;" : "=f"(lo), "=f"(hi) : "l"(in))

__device__ __forceinline__ int lower_bound_s(const float* c, float v) {
  int lo = 0, hi = TT;
  while (lo < hi) { int m = (lo + hi) >> 1; if (c[m] < v) lo = m + 1; else hi = m; }
  return lo;
}

// ---------------------------------------------------------------------------
// Brent-Kung scan replicating jax.lax.associative_scan's exact add tree,
// then per-tile band computation. 16 blocks x 256 threads (best measured).
// ---------------------------------------------------------------------------
__global__ void cumsum_kernel(const float* __restrict__ w) {
  __shared__ float buf[1024];
  __shared__ float c_sh[TT];
  const int b = blockIdx.x;
  const int tid = threadIdx.x;
  const float* wb = w + b * TT;

  for (int i = tid; i < TT; i += blockDim.x) buf[i] = wb[i];
  __syncthreads();

  for (int size = TT; size > 1; size >>= 1) {   // up-sweep
    int off = 1024 - 2 * size, noff = 1024 - size, half = size >> 1;
    for (int i = tid; i < half; i += blockDim.x)
      buf[noff + i] = buf[off + 2 * i] + buf[off + 2 * i + 1];
    __syncthreads();
  }
  for (int size = 2; size <= TT; size <<= 1) {  // down-sweep
    int off = 1024 - 2 * size, offp = 1024 - size, half = size >> 1;
    for (int i = tid; i < half; i += blockDim.x) {
      float sp = buf[offp + i];
      if (2 * i + 2 < size) {
        float t = sp + buf[off + 2 * i + 2];
        buf[off + 2 * i + 1] = sp;
        buf[off + 2 * i + 2] = t;
      } else {
        buf[off + 2 * i + 1] = sp;
      }
    }
    __syncthreads();
  }
  for (int i = tid; i < TT; i += blockDim.x) {
    float cv = buf[i] - 0.5f * wb[i];
    c_sh[i] = cv;
    g_c[b * TT + i] = cv;
  }
  __syncthreads();

  for (int t = tid; t < NTILES; t += blockDim.x) {
    const float R = 18.0f;  // exp(-0.1*18^2) ~ 8e-15 relative
    float tmin = (float)(t * TILE_F);
    float tmax = tmin + (float)(TILE_F - 1);
    int jlo = lower_bound_s(c_sh, tmin - R);
    int jhi = lower_bound_s(c_sh, tmax + R);
    int plo = lower_bound_s(c_sh, tmin);
    int phi = lower_bound_s(c_sh, tmax);
    jlo = min(jlo, max(plo - 1, 0));          // always include nearest tokens
    jhi = max(jhi, min(phi + 1, TT));
    jlo &= ~3;                                 // float4 alignment
    if (jhi - jlo > MAXBAND) {                 // statistically impossible cap
      int slack = (max(0, (plo - 1) - jlo)) & ~3;
      int need  = jhi - jlo - MAXBAND;
      int adv   = min((need + 3) & ~3, slack);
      jlo += adv;
      jhi = min(jhi, jlo + MAXBAND);
    }
    g_band[b * NTILES + t] = make_int2(jlo, jhi);
  }
}

// ---------------------------------------------------------------------------
// Fused banded softmax + GEMM. Block = (16-frame tile, batch), 256 threads,
// full 256 channels. Thread tile 2ch x 8fr; regs <= 64 -> 4 CTAs/SM.
// x_s[tok][256ch], token-major, R5 XOR swizzle (store col = 4*((c>>2)^tq)+(c&3)).
// ---------------------------------------------------------------------------
__global__ __launch_bounds__(NTHREADS, 4) void gauss_kernel(
    const float* __restrict__ x, float* __restrict__ out)
{
  __shared__ __align__(16) float x_s[MAXBAND][NC];        // 32 KB, swizzled
  __shared__ __align__(16) float attn_s[MAXBAND][TILE_F]; // unnormalized E
  __shared__ float c_sh[MAXBAND];
  __shared__ float ps[16][TILE_F];
  __shared__ __align__(16) float r_s[TILE_F];

  const int b   = blockIdx.y;
  const int f0  = blockIdx.x * TILE_F;
  const int tid = threadIdx.x;

  const int2 bd = g_band[b * NTILES + blockIdx.x];
  const int jlo = bd.x;
  const int nband  = bd.y - jlo;
  const int nband4 = (nband + 3) & ~3;

  // ---- phase A: issue x loads (8 float4: 8 channels x 4 tokens) --------
  const int cl  = tid & 3;
  const int tq  = (tid >> 2) & 7;
  const int rep = tid >> 5;          // 0..7
  const int row0 = 4 * tq;
  const bool doload = row0 < nband4;
  float4 v[8];
  if (doload) {
    const bool full = (row0 + 4 <= nband);
    const float* xb = x + (size_t)b * NC * TT + jlo + row0;
    #pragma unroll
    for (int p = 0; p < 8; p++) {
      const int c = cl + 4 * rep + 32 * p;
      const float* src = xb + (size_t)c * TT;
      if (full) {
        v[p] = *(const float4*)src;
      } else {
        v[p].x = (row0     < nband) ? src[0] : 0.0f;
        v[p].y = (row0 + 1 < nband) ? src[1] : 0.0f;
        v[p].z = (row0 + 2 < nband) ? src[2] : 0.0f;
        v[p].w = (row0 + 3 < nband) ? src[3] : 0.0f;
      }
    }
  }

  if (tid < MAXBAND)
    c_sh[tid] = (tid < nband) ? g_c[b * TT + jlo + tid] : 3.0e38f;
  __syncthreads();                                   // #1: c_sh ready

  // ---- phase B: analytic softmax max + exp + partial sums; x STS -------
  const int fE   = tid & 15;         // frame within tile
  const int kgrp = tid >> 4;         // 0..15
  {
    const float tf = (float)(f0 + fE);
    int lo = 0, hi = nband;          // nearest center (<=5 steps)
    while (lo < hi) { int mid = (lo + hi) >> 1; if (c_sh[mid] < tf) lo = mid + 1; else hi = mid; }
    float dR = (lo < nband) ? (c_sh[lo] - tf) : 3.0e38f;
    float dL = (lo > 0)     ? (tf - c_sh[lo - 1]) : 3.0e38f;
    float dmin = fminf(dL, dR);
    const float m = -DELTA_F * (dmin * dmin);        // exact band max

    float sloc = 0.0f;
    #pragma unroll
    for (int u = 0; u < 2; u++) {
      const int kk = kgrp + 16 * u;
      float E = 0.0f;
      if (kk < nband) {
        float d = tf - c_sh[kk];
        E = __expf(-DELTA_F * (d * d) - m);          // <= 1, NaN-safe
      }
      attn_s[kk][fE] = E;
      sloc += E;
    }
    ps[kgrp][fE] = sloc;
  }
  if (doload) {
    #pragma unroll
    for (int p = 0; p < 8; p++) {
      const int cq  = rep + 8 * p;                   // = c>>2
      const int col = 4 * (cq ^ tq) + cl;            // XOR swizzle: conflict-free
      x_s[row0 + 0][col] = v[p].x;
      x_s[row0 + 1][col] = v[p].y;
      x_s[row0 + 2][col] = v[p].z;
      x_s[row0 + 3][col] = v[p].w;
    }
  }
  __syncthreads();                                   // #2: attn_s, x_s, ps ready
  if (tid < TILE_F) {
    float s = ps[0][tid];
    #pragma unroll
    for (int k = 1; k < 16; k++) s += ps[k][tid];
    r_s[tid] = 1.0f / s;
  }

  // ---- main FMA loop (unnormalized) ------------------------------------
  const int cgrp = tid >> 1;          // 0..127: channels 2*cgrp, 2*cgrp+1
  const int fg   = (tid & 1) << 3;    // frame base (8 frames)

  unsigned long long acc2[2][4];
  #pragma unroll
  for (int ci = 0; ci < 2; ci++)
    #pragma unroll
    for (int q = 0; q < 4; q++) acc2[ci][q] = 0ull;

  for (int kk0 = 0; kk0 < nband4; kk0 += 4) {
    const int colb = 4 * ((cgrp >> 1) ^ (kk0 >> 2)) + 2 * (cgrp & 1);
    #pragma unroll
    for (int u = 0; u < 4; u++) {
      const int kk = kk0 + u;
      float2 xv = *(const float2*)&x_s[kk][colb];
      ulonglong2 a01 = *(const ulonglong2*)&attn_s[kk][fg];
      ulonglong2 a23 = *(const ulonglong2*)&attn_s[kk][fg + 4];
      unsigned long long xp0, xp1;
      PACK2(xp0, xv.x, xv.x);
      PACK2(xp1, xv.y, xv.y);
      FMA2(acc2[0][0], xp0, a01.x);
      FMA2(acc2[0][1], xp0, a01.y);
      FMA2(acc2[0][2], xp0, a23.x);
      FMA2(acc2[0][3], xp0, a23.y);
      FMA2(acc2[1][0], xp1, a01.x);
      FMA2(acc2[1][1], xp1, a01.y);
      FMA2(acc2[1][2], xp1, a23.x);
      FMA2(acc2[1][3], xp1, a23.y);
    }
  }
  __syncthreads();                                   // #3: r_s ready

  // ---- epilogue: normalize by r[f], store ------------------------------
  ulonglong2 r01 = *(const ulonglong2*)&r_s[fg];
  ulonglong2 r23 = *(const ulonglong2*)&r_s[fg + 4];
  unsigned long long rp[4] = {r01.x, r01.y, r23.x, r23.y};

  #pragma unroll
  for (int ci = 0; ci < 2; ci++) {
    float r[8];
    #pragma unroll
    for (int q = 0; q < 4; q++) {
      unsigned long long t;
      MUL2(t, acc2[ci][q], rp[q]);
      UNPACK2(r[2 * q], r[2 * q + 1], t);
    }
    const int ch = 2 * cgrp + ci;
    float* o = out + ((size_t)b * NC + ch) * TFEAT + f0 + fg;
    *(float4*)&o[0] = make_float4(r[0], r[1], r[2], r[3]);
    *(float4*)&o[4] = make_float4(r[4], r[5], r[6], r[7]);
  }
}

extern "C" void kernel_launch(void* const* d_in, const int* in_sizes, int n_in,
                              void* d_out, int out_size) {
  const float* x = (const float*)d_in[0];   // (B, C, T_text) fp32
  const float* w = (const float*)d_in[1];   // (B, T_text)    fp32
  float* out = (float*)d_out;               // (B, C, T_feat) fp32

  cumsum_kernel<<<NB, 256>>>(w);
  gauss_kernel<<<dim3(NTILES, NB), NTHREADS>>>(x, out);
}

// round 11
// speedup vs baseline: 1.1466x; 1.1404x over previous
#include <cuda_runtime.h>

// GaussianUpsampling: out[b,c,f] = sum_j softmax_j(-0.1*(f - c_j)^2) * x[b,c,j]
//   c = cumsum(w) - 0.5*w   (bit-matches JAX associative_scan Brent-Kung tree)
// B=16, C=256, T_text=512, T_feat=4096. Masks structurally all-true.
//
// R11: gauss = R8 (best measured). cumsum = register-resident Brent-Kung:
// warp 0 keeps 16 elems/lane in regs; in-lane up-sweep, 5-level cross-lane
// BK on lane sums via shfl, in-lane down-sweep. Same add tree -> bit-exact.
// Bands computed by all 256 threads (1 tile each).

#define NB 16
#define NC 256
#define NCH 128            // channels per CTA
#define TT 512
#define TFEAT 4096
#define DELTA_F 0.1f
#define TILE_F 32
#define NTILES (TFEAT / TILE_F)   // 128
#define MAXBAND 32
#define NTHREADS 256
#define FULLW 0xffffffffu

__device__ float g_c[NB * TT];
__device__ int2  g_band[NB * NTILES];

#define FMA2(acc, a, b) \
  asm("fma.rn.f32x2 %0, %1, %2, %0;" : "+l"(acc) : "l"(a), "l"(b))
#define MUL2(out, a, b) \
  asm("mul.rn.f32x2 %0, %1, %2;" : "=l"(out) : "l"(a), "l"(b))
#define PACK2(out, lo, hi) \
  asm("mov.b64 %0, {%1, %2};" : "=l"(out) : "f"(lo), "f"(hi))
#define UNPACK2(lo, hi, in) \
  asm("mov.b64 {%0, %1}, %2;" : "=f"(lo), "=f"(hi) : "l"(in))

__device__ __forceinline__ int lower_bound_s(const float* c, float v) {
  int lo = 0, hi = TT;
  while (lo < hi) { int m = (lo + hi) >> 1; if (c[m] < v) lo = m + 1; else hi = m; }
  return lo;
}

// ---------------------------------------------------------------------------
// Register Brent-Kung scan (warp 0) + parallel band computation (256 thr).
// Tree identical to jax.lax.associative_scan's -> bit-exact c values.
// ---------------------------------------------------------------------------
__global__ void cumsum_kernel(const float* __restrict__ w) {
  __shared__ float c_sh[TT];
  const int b   = blockIdx.x;
  const int tid = threadIdx.x;

  if (tid < 32) {
    const int lane = tid;
    const float* wb = w + b * TT + 16 * lane;
    float b0[16];
    #pragma unroll
    for (int q = 0; q < 4; q++) {
      float4 t4 = *(const float4*)(wb + 4 * q);
      b0[4 * q] = t4.x; b0[4 * q + 1] = t4.y; b0[4 * q + 2] = t4.z; b0[4 * q + 3] = t4.w;
    }
    // in-lane up-sweep (levels 0->4)
    float b1[8], b2[4], b3[2], B4;
    #pragma unroll
    for (int j = 0; j < 8; j++) b1[j] = b0[2 * j] + b0[2 * j + 1];
    #pragma unroll
    for (int j = 0; j < 4; j++) b2[j] = b1[2 * j] + b1[2 * j + 1];
    #pragma unroll
    for (int j = 0; j < 2; j++) b3[j] = b2[2 * j] + b2[2 * j + 1];
    B4 = b3[0] + b3[1];
    // cross-lane up-sweep (levels 5->9); B_l valid on lanes % 2^(l-4) == 0
    float B5 = B4 + __shfl_down_sync(FULLW, B4, 1);
    float B6 = B5 + __shfl_down_sync(FULLW, B5, 2);
    float B7 = B6 + __shfl_down_sync(FULLW, B6, 4);
    float B8 = B7 + __shfl_down_sync(FULLW, B7, 8);
    float B9 = B8 + __shfl_down_sync(FULLW, B8, 16);
    // cross-lane down-sweep: Sv = S_l[k] on lanes k*s; rules:
    //   k==0 -> B_l ; k odd -> S_{l+1}[(k-1)/2] (lane j-s) ;
    //   k even>0 -> S_{l+1}[(k-2)/2] (lane j-2s) + B_l
    float Sv = B9;                         // level 9, lane 0
    #pragma unroll
    for (int lvl = 8; lvl >= 4; lvl--) {
      const int s = 1 << (lvl - 4);
      const float bl = (lvl == 8) ? B8 : (lvl == 7) ? B7 : (lvl == 6) ? B6
                     : (lvl == 5) ? B5 : B4;
      float up1 = __shfl_sync(FULLW, Sv, (lane >= s) ? lane - s : 0);
      float up2 = __shfl_sync(FULLW, Sv, (lane >= 2 * s) ? lane - 2 * s : 0);
      if ((lane & (s - 1)) == 0) {
        const int k = lane / s;
        Sv = (k == 0) ? bl : ((k & 1) ? up1 : up2 + bl);
      }
    }
    // Sv = inclusive BK scan of lane sums. P = exclusive lane prefix.
    float P = __shfl_up_sync(FULLW, Sv, 1);
    const bool l0 = (lane == 0);
    // in-lane down-sweep
    float S3_0 = l0 ? b3[0] : P + b3[0];
    float S3_1 = Sv;
    float S2_0 = l0 ? b2[0] : P + b2[0];
    float S2_1 = S3_0;
    float S2_2 = S3_0 + b2[2];
    float S2_3 = S3_1;
    float S1[8];
    S1[0] = l0 ? b1[0] : P + b1[0];
    S1[1] = S2_0;
    S1[2] = S2_0 + b1[2];
    S1[3] = S2_1;
    S1[4] = S2_1 + b1[4];
    S1[5] = S2_2;
    S1[6] = S2_2 + b1[6];
    S1[7] = S2_3;
    float s[16];
    s[0] = l0 ? b0[0] : P + b0[0];
    #pragma unroll
    for (int m = 1; m < 16; m += 2) s[m] = S1[(m - 1) >> 1];
    #pragma unroll
    for (int m = 2; m < 16; m += 2) s[m] = S1[(m - 2) >> 1] + b0[m];
    // c = scan - 0.5*w
    float cv[16];
    #pragma unroll
    for (int m = 0; m < 16; m++) cv[m] = s[m] - 0.5f * b0[m];
    float* gc = g_c + b * TT + 16 * lane;
    #pragma unroll
    for (int q = 0; q < 4; q++) {
      float4 t4 = make_float4(cv[4 * q], cv[4 * q + 1], cv[4 * q + 2], cv[4 * q + 3]);
      *(float4*)(&c_sh[16 * lane + 4 * q]) = t4;
      *(float4*)(gc + 4 * q) = t4;
    }
  }
  __syncthreads();

  // bands: one 32-frame tile per thread (tid < 128)
  if (tid < NTILES) {
    const int t = tid;
    const float R = 18.0f;  // exp(-0.1*18^2) ~ 8e-15 relative
    float tmin = (float)(t * TILE_F);
    float tmax = tmin + (float)(TILE_F - 1);
    int jlo = lower_bound_s(c_sh, tmin - R);
    int jhi = lower_bound_s(c_sh, tmax + R);
    int plo = lower_bound_s(c_sh, tmin);
    int phi = lower_bound_s(c_sh, tmax);
    jlo = min(jlo, max(plo - 1, 0));          // always include nearest tokens
    jhi = max(jhi, min(phi + 1, TT));
    jlo &= ~3;                                 // float4 alignment
    if (jhi - jlo > MAXBAND) {                 // statistically impossible cap
      int slack = (max(0, (plo - 1) - jlo)) & ~3;
      int need  = jhi - jlo - MAXBAND;
      int adv   = min((need + 3) & ~3, slack);
      jlo += adv;
      jhi = min(jhi, jlo + MAXBAND);
    }
    g_band[b * NTILES + t] = make_int2(jlo, jhi);
  }
}

// ---------------------------------------------------------------------------
// Fused banded softmax + GEMM (R8 — best measured, unchanged).
// Block = (32-frame tile, channel half, batch). 256 threads,
// thread tile 2ch x 8fr, regs <= 64, 4 CTAs/SM. Analytic softmax max.
// ---------------------------------------------------------------------------
__global__ __launch_bounds__(NTHREADS, 4) void gauss_kernel(
    const float* __restrict__ x, float* __restrict__ out)
{
  __shared__ __align__(16) float x_s[MAXBAND][NCH];      // XOR-swizzled
  __shared__ __align__(16) float attn_s[MAXBAND][TILE_F]; // unnormalized E
  __shared__ float c_sh[MAXBAND];
  __shared__ float ps[8][TILE_F];
  __shared__ __align__(16) float r_s[TILE_F];

  const int b    = blockIdx.z;
  const int half = blockIdx.y;
  const int f0   = blockIdx.x * TILE_F;
  const int tid  = threadIdx.x;

  const int2 bd = g_band[b * NTILES + blockIdx.x];
  const int jlo = bd.x;
  const int nband  = bd.y - jlo;
  const int nband4 = (nband + 3) & ~3;

  // ---- phase A: issue x loads into registers ---------------------------
  const int cl  = tid & 3;
  const int tq  = (tid >> 2) & 7;
  const int rep = tid >> 5;          // 0..7
  const int row0 = 4 * tq;
  const bool doload = row0 < nband4;
  float v[4][4];
  if (doload) {
    const bool full = (row0 + 4 <= nband);
    const float* xb = x + ((size_t)b * NC + half * NCH) * TT + jlo + row0;
    #pragma unroll
    for (int p = 0; p < 4; p++) {
      const int c = cl + 4 * rep + 32 * p;
      const float* src = xb + (size_t)c * TT;
      if (full) {
        float4 t4 = *(const float4*)src;
        v[p][0] = t4.x; v[p][1] = t4.y; v[p][2] = t4.z; v[p][3] = t4.w;
      } else {
        v[p][0] = (row0     < nband) ? src[0] : 0.0f;
        v[p][1] = (row0 + 1 < nband) ? src[1] : 0.0f;
        v[p][2] = (row0 + 2 < nband) ? src[2] : 0.0f;
        v[p][3] = (row0 + 3 < nband) ? src[3] : 0.0f;
      }
    }
  }

  if (tid < MAXBAND)
    c_sh[tid] = (tid < nband) ? g_c[b * TT + jlo + tid] : 3.0e38f;
  __syncthreads();                                   // #1: c_sh ready

  // ---- phase B: analytic softmax max + exp + partial sums; x STS -------
  const int fE   = tid & 31;         // frame within tile
  const int kgrp = tid >> 5;         // 0..7
  {
    const float tf = (float)(f0 + fE);
    int lo = 0, hi = nband;          // nearest center (<=5 steps)
    while (lo < hi) { int mid = (lo + hi) >> 1; if (c_sh[mid] < tf) lo = mid + 1; else hi = mid; }
    float dR = (lo < nband) ? (c_sh[lo] - tf) : 3.0e38f;
    float dL = (lo > 0)     ? (tf - c_sh[lo - 1]) : 3.0e38f;
    float dmin = fminf(dL, dR);
    const float m = -DELTA_F * (dmin * dmin);        // exact band max

    float sloc = 0.0f;
    #pragma unroll
    for (int u = 0; u < 4; u++) {
      const int kk = kgrp + 8 * u;
      float E = 0.0f;
      if (kk < nband) {
        float d = tf - c_sh[kk];
        E = __expf(-DELTA_F * (d * d) - m);          // <= 1, NaN-safe
      }
      attn_s[kk][fE] = E;
      sloc += E;
    }
    ps[kgrp][fE] = sloc;
  }
  if (doload) {
    #pragma unroll
    for (int p = 0; p < 4; p++) {
      const int cq  = rep + 8 * p;
      const int col = 4 * (cq ^ tq) + cl;            // XOR swizzle: conflict-free
      #pragma unroll
      for (int r = 0; r < 4; r++) x_s[row0 + r][col] = v[p][r];
    }
  }
  __syncthreads();                                   // #2: attn_s, x_s, ps ready
  if (tid < TILE_F) {
    float s = ps[0][tid];
    #pragma unroll
    for (int k = 1; k < 8; k++) s += ps[k][tid];
    r_s[tid] = 1.0f / s;
  }

  // ---- main FMA loop (unnormalized) ------------------------------------
  const int cgrp = tid >> 2;          // 0..63: channel pair 2*cgrp, 2*cgrp+1
  const int fg   = (tid & 3) << 3;    // frame base (8 frames)

  unsigned long long acc2[2][4];
  #pragma unroll
  for (int ci = 0; ci < 2; ci++)
    #pragma unroll
    for (int q = 0; q < 4; q++) acc2[ci][q] = 0ull;

  for (int kk0 = 0; kk0 < nband4; kk0 += 4) {
    const int colb = 4 * ((cgrp >> 1) ^ (kk0 >> 2)) + 2 * (cgrp & 1);
    #pragma unroll
    for (int u = 0; u < 4; u++) {
      const int kk = kk0 + u;
      float2 xv = *(const float2*)&x_s[kk][colb];
      ulonglong2 a01 = *(const ulonglong2*)&attn_s[kk][fg];
      ulonglong2 a23 = *(const ulonglong2*)&attn_s[kk][fg + 4];
      unsigned long long xp0, xp1;
      PACK2(xp0, xv.x, xv.x);
      PACK2(xp1, xv.y, xv.y);
      FMA2(acc2[0][0], xp0, a01.x);
      FMA2(acc2[0][1], xp0, a01.y);
      FMA2(acc2[0][2], xp0, a23.x);
      FMA2(acc2[0][3], xp0, a23.y);
      FMA2(acc2[1][0], xp1, a01.x);
      FMA2(acc2[1][1], xp1, a01.y);
      FMA2(acc2[1][2], xp1, a23.x);
      FMA2(acc2[1][3], xp1, a23.y);
    }
  }
  __syncthreads();                                   // #3: r_s ready

  // ---- epilogue: normalize by r[f], store ------------------------------
  ulonglong2 r01 = *(const ulonglong2*)&r_s[fg];
  ulonglong2 r23 = *(const ulonglong2*)&r_s[fg + 4];
  unsigned long long rp[4] = {r01.x, r01.y, r23.x, r23.y};

  #pragma unroll
  for (int ci = 0; ci < 2; ci++) {
    float r[8];
    #pragma unroll
    for (int q = 0; q < 4; q++) {
      unsigned long long t;
      MUL2(t, acc2[ci][q], rp[q]);
      UNPACK2(r[2 * q], r[2 * q + 1], t);
    }
    const int ch = half * NCH + 2 * cgrp + ci;
    float* o = out + ((size_t)b * NC + ch) * TFEAT + f0 + fg;
    *(float4*)&o[0] = make_float4(r[0], r[1], r[2], r[3]);
    *(float4*)&o[4] = make_float4(r[4], r[5], r[6], r[7]);
  }
}

extern "C" void kernel_launch(void* const* d_in, const int* in_sizes, int n_in,
                              void* d_out, int out_size) {
  const float* x = (const float*)d_in[0];   // (B, C, T_text) fp32
  const float* w = (const float*)d_in[1];   // (B, T_text)    fp32
  float* out = (float*)d_out;               // (B, C, T_feat) fp32

  cumsum_kernel<<<NB, NTHREADS>>>(w);
  gauss_kernel<<<dim3(NTILES, 2, NB), NTHREADS>>>(x, out);
}